// round 12
// baseline (speedup 1.0000x reference)
#include <cuda_runtime.h>

// VecInt: scaling-and-squaring integration of a stationary velocity field.
// vec (1,3,160,192,160) fp32, nsteps=7.
//
// Round 12: R11 (pair-lane gather + PDL chain, 496.8us) with two micro-levers:
//  (a) y-pair blocks: 640 threads cover two adjacent y-rows, capturing the
//      overlapping trilinear corner windows of y and y+1 in the SAME SM's L1
//      (tests whether l1tex 92.5% includes a reducible miss-handling term).
//  (b) LAST-kernel egress split across pair lanes (both lanes hold the
//      reduced sum after shfl_xor; sub0 writes ch0/ch1, sub1 writes ch2).
// Arithmetic bit-identical to R11.

constexpr int D = 160;
constexpr int H = 192;
constexpr int W = 160;
constexpr int NVOX = D * H * W;          // 4,915,200
constexpr int NSTEPS = 7;

__device__ __align__(128) float4 g_bufA[NVOX];
__device__ __align__(128) float4 g_bufB[NVOX];

__device__ __forceinline__ void pdl_launch_dependents() {
    asm volatile("griddepcontrol.launch_dependents;" ::: "memory");
}
__device__ __forceinline__ void pdl_wait() {
    asm volatile("griddepcontrol.wait;" ::: "memory");
}

// ---------------------------------------------------------------------------
// Iteration 1, fused with SoA ingest + per-channel voxel-unit scaling.
// One thread per voxel, block = one x-row (160 threads), grid = (H, D).
// ---------------------------------------------------------------------------
__global__ void __launch_bounds__(160)
iter1_kernel(const float* __restrict__ in, float4* __restrict__ out)
{
    int x = threadIdx.x;
    int y = blockIdx.x;
    int z = blockIdx.y;
    int idx = (z * H + y) * W + x;

    pdl_launch_dependents();   // input is external; just let iter2 spin up

    const float s  = 1.0f / 128.0f;          // 1/2^7
    const float sD = s * 0.5f * (D - 1);
    const float sH = s * 0.5f * (H - 1);
    const float sW = s * 0.5f * (W - 1);

    const float* p0 = in;
    const float* p1 = in + NVOX;
    const float* p2 = in + 2 * NVOX;

    float vx = p0[idx] * sD;
    float vy = p1[idx] * sH;
    float vz = p2[idx] * sW;

    float zf = (float)z + vx;
    float yf = (float)y + vy;
    float xf = (float)x + vz;

    int z0 = __float2int_rd(zf);
    int y0 = __float2int_rd(yf);
    int x0 = __float2int_rd(xf);
    float fz = zf - (float)z0;
    float fy = yf - (float)y0;
    float fx = xf - (float)x0;
    int z1 = z0 + 1, y1 = y0 + 1;

    float Wz0 = ((unsigned)z0 < (unsigned)D) ? (1.0f - fz) : 0.0f;
    float Wz1 = ((unsigned)z1 < (unsigned)D) ? fz          : 0.0f;
    float Wy0 = ((unsigned)y0 < (unsigned)H) ? (1.0f - fy) : 0.0f;
    float Wy1 = ((unsigned)y1 < (unsigned)H) ? fy          : 0.0f;
    float Wx0 = ((unsigned)x0 < (unsigned)W) ? (1.0f - fx) : 0.0f;
    float Wx1 = ((unsigned)(x0 + 1) < (unsigned)W) ? fx    : 0.0f;

    int zc0 = min(max(z0, 0), D - 1), zc1 = min(max(z1, 0), D - 1);
    int yc0 = min(max(y0, 0), H - 1), yc1 = min(max(y1, 0), H - 1);
    int xc0 = min(max(x0, 0), W - 1), xc1 = min(max(x0 + 1, 0), W - 1);

    int r00 = (zc0 * H + yc0) * W;
    int r01 = (zc0 * H + yc1) * W;
    int r10 = (zc1 * H + yc0) * W;
    int r11 = (zc1 * H + yc1) * W;

    float px, py, pz;
    {
        const float* p = p0; const float sc = sD;
        float c00a = p[r00 + xc0] * sc, c00b = p[r00 + xc1] * sc;
        float c01a = p[r01 + xc0] * sc, c01b = p[r01 + xc1] * sc;
        float c10a = p[r10 + xc0] * sc, c10b = p[r10 + xc1] * sc;
        float c11a = p[r11 + xc0] * sc, c11b = p[r11 + xc1] * sc;
        float a0A = fmaf(c01a, Wy1, c00a * Wy0);
        float a1A = fmaf(c11a, Wy1, c10a * Wy0);
        float a0B = fmaf(c01b, Wy1, c00b * Wy0);
        float a1B = fmaf(c11b, Wy1, c10b * Wy0);
        px = Wx0 * fmaf(a1A, Wz1, a0A * Wz0)
           + Wx1 * fmaf(a1B, Wz1, a0B * Wz0);
    }
    {
        const float* p = p1; const float sc = sH;
        float c00a = p[r00 + xc0] * sc, c00b = p[r00 + xc1] * sc;
        float c01a = p[r01 + xc0] * sc, c01b = p[r01 + xc1] * sc;
        float c10a = p[r10 + xc0] * sc, c10b = p[r10 + xc1] * sc;
        float c11a = p[r11 + xc0] * sc, c11b = p[r11 + xc1] * sc;
        float a0A = fmaf(c01a, Wy1, c00a * Wy0);
        float a1A = fmaf(c11a, Wy1, c10a * Wy0);
        float a0B = fmaf(c01b, Wy1, c00b * Wy0);
        float a1B = fmaf(c11b, Wy1, c10b * Wy0);
        py = Wx0 * fmaf(a1A, Wz1, a0A * Wz0)
           + Wx1 * fmaf(a1B, Wz1, a0B * Wz0);
    }
    {
        const float* p = p2; const float sc = sW;
        float c00a = p[r00 + xc0] * sc, c00b = p[r00 + xc1] * sc;
        float c01a = p[r01 + xc0] * sc, c01b = p[r01 + xc1] * sc;
        float c10a = p[r10 + xc0] * sc, c10b = p[r10 + xc1] * sc;
        float c11a = p[r11 + xc0] * sc, c11b = p[r11 + xc1] * sc;
        float a0A = fmaf(c01a, Wy1, c00a * Wy0);
        float a1A = fmaf(c11a, Wy1, c10a * Wy0);
        float a0B = fmaf(c01b, Wy1, c00b * Wy0);
        float a1B = fmaf(c11b, Wy1, c10b * Wy0);
        pz = Wx0 * fmaf(a1A, Wz1, a0A * Wz0)
           + Wx1 * fmaf(a1B, Wz1, a0B * Wz0);
    }

    out[idx] = make_float4(vx + px, vy + py, vz + pz, 0.0f);
}

// ---------------------------------------------------------------------------
// Iterations 2-7: pair-lane scheme, y-pair blocks.
// Block = two x-rows: threadIdx.y in {0,1} selects the y row,
// blockIdx.x = y-pair, blockIdx.y = z. 640 threads.
// Within a row: 320 threads = 160 voxels * 2 lanes (sub0 -> x0, sub1 -> x1).
// ---------------------------------------------------------------------------
template<bool LAST>
__global__ void __launch_bounds__(640)
integrate_kernel(const float4* __restrict__ in, float4* __restrict__ out4,
                 float* __restrict__ out_soa)
{
    int x   = threadIdx.x >> 1;
    int sub = threadIdx.x & 1;
    int y   = blockIdx.x * 2 + threadIdx.y;
    int z   = blockIdx.y;
    int idx = (z * H + y) * W + x;

    pdl_launch_dependents();
    pdl_wait();

    float4 v = in[idx];   // same address in both pair lanes -> broadcast

    float zf = (float)z + v.x;
    float yf = (float)y + v.y;
    float xf = (float)x + v.z;

    int z0 = __float2int_rd(zf);
    int y0 = __float2int_rd(yf);
    int x0 = __float2int_rd(xf);
    float fz = zf - (float)z0;
    float fy = yf - (float)y0;
    float fx = xf - (float)x0;
    int z1 = z0 + 1, y1 = y0 + 1;

    float Wz0 = ((unsigned)z0 < (unsigned)D) ? (1.0f - fz) : 0.0f;
    float Wz1 = ((unsigned)z1 < (unsigned)D) ? fz          : 0.0f;
    float Wy0 = ((unsigned)y0 < (unsigned)H) ? (1.0f - fy) : 0.0f;
    float Wy1 = ((unsigned)y1 < (unsigned)H) ? fy          : 0.0f;
    float Wx0 = ((unsigned)x0 < (unsigned)W) ? (1.0f - fx) : 0.0f;
    float Wx1 = ((unsigned)(x0 + 1) < (unsigned)W) ? fx    : 0.0f;

    int zc0 = min(max(z0, 0), D - 1), zc1 = min(max(z1, 0), D - 1);
    int yc0 = min(max(y0, 0), H - 1), yc1 = min(max(y1, 0), H - 1);
    int xc0 = min(max(x0, 0), W - 1), xc1 = min(max(x0 + 1, 0), W - 1);

    int   xc = sub ? xc1 : xc0;
    float wx = sub ? Wx1 : Wx0;

    int r00 = (zc0 * H + yc0) * W + xc;
    int r01 = (zc0 * H + yc1) * W + xc;
    int r10 = (zc1 * H + yc0) * W + xc;
    int r11 = (zc1 * H + yc1) * W + xc;

    float4 c00 = in[r00];
    float4 c01 = in[r01];
    float4 c10 = in[r10];
    float4 c11 = in[r11];

    float px, py, pz;
    {
        float a0 = fmaf(c01.x, Wy1, c00.x * Wy0);
        float a1 = fmaf(c11.x, Wy1, c10.x * Wy0);
        px = wx * fmaf(a1, Wz1, a0 * Wz0);
    }
    {
        float a0 = fmaf(c01.y, Wy1, c00.y * Wy0);
        float a1 = fmaf(c11.y, Wy1, c10.y * Wy0);
        py = wx * fmaf(a1, Wz1, a0 * Wz0);
    }
    {
        float a0 = fmaf(c01.z, Wy1, c00.z * Wy0);
        float a1 = fmaf(c11.z, Wy1, c10.z * Wy0);
        pz = wx * fmaf(a1, Wz1, a0 * Wz0);
    }
    px += __shfl_xor_sync(0xFFFFFFFFu, px, 1);
    py += __shfl_xor_sync(0xFFFFFFFFu, py, 1);
    pz += __shfl_xor_sync(0xFFFFFFFFu, pz, 1);

    if (!LAST) {
        if (sub == 0) {
            float4 r;
            r.x = v.x + px;
            r.y = v.y + py;
            r.z = v.z + pz;
            r.w = 0.0f;
            out4[idx] = r;
        }
    } else {
        // both lanes hold the reduced sums; split the 3 plane stores
        if (sub == 0) {
            out_soa[idx]            = (v.x + px) * (1.0f / (0.5f * (D - 1)));
            out_soa[idx + NVOX]     = (v.y + py) * (1.0f / (0.5f * (H - 1)));
        } else {
            out_soa[idx + 2 * NVOX] = (v.z + pz) * (1.0f / (0.5f * (W - 1)));
        }
    }
}

static void launch_pdl(void* func, dim3 grid, dim3 block, void** args)
{
    cudaLaunchConfig_t cfg = {};
    cfg.gridDim  = grid;
    cfg.blockDim = block;
    cfg.dynamicSmemBytes = 0;
    cfg.stream = 0;
    cudaLaunchAttribute attr[1];
    attr[0].id = cudaLaunchAttributeProgrammaticStreamSerialization;
    attr[0].val.programmaticStreamSerializationAllowed = 1;
    cfg.attrs = attr;
    cfg.numAttrs = 1;
    cudaLaunchKernelExC(&cfg, func, args);
}

extern "C" void kernel_launch(void* const* d_in, const int* in_sizes, int n_in,
                              void* d_out, int out_size)
{
    const float* vec = (const float*)d_in[0];
    float* out = (float*)d_out;

    float4 *bufA, *bufB;
    cudaGetSymbolAddress((void**)&bufA, g_bufA);
    cudaGetSymbolAddress((void**)&bufB, g_bufB);

    dim3 grid1(H, D);                // (y, z) — iter1
    dim3 gridI(H / 2, D);            // (y-pair, z) — iters 2..7
    dim3 blockI(2 * W, 2);           // 640 threads: 2 rows x (160 vox * 2 lanes)

    // iteration 1, fused with ingest/scaling
    {
        const float* a0 = vec; float4* a1 = bufA;
        void* args[] = { &a0, &a1 };
        launch_pdl((void*)iter1_kernel, grid1, dim3(W), args);
    }

    // iterations 2..6
    float4* cur = bufA;
    float4* nxt = bufB;
    for (int i = 0; i < NSTEPS - 2; ++i) {
        const float4* a0 = cur; float4* a1 = nxt; float* a2 = nullptr;
        void* args[] = { &a0, &a1, &a2 };
        launch_pdl((void*)integrate_kernel<false>, gridI, blockI, args);
        float4* tmp = cur; cur = nxt; nxt = tmp;
    }
    // iteration 7, fused with SoA scale-out
    {
        const float4* a0 = cur; float4* a1 = nullptr; float* a2 = out;
        void* args[] = { &a0, &a1, &a2 };
        launch_pdl((void*)integrate_kernel<true>, gridI, blockI, args);
    }
}

// round 13
// speedup vs baseline: 1.0205x; 1.0205x over previous
#include <cuda_runtime.h>

// VecInt: scaling-and-squaring integration of a stationary velocity field.
// vec (1,3,160,192,160) fp32, nsteps=7.
//
// Round 13: exact R11 restoration (proven best, 496.8us): pair-lane gather
// (320-thread blocks, one x-row per block) + PDL-chained launches. R12
// proved the L1tex crossbar issue rate alone binds (y-pair blocks cut L2
// traffic 57.7->46.3% with no time win), so the R11 grid shape stands.
// Single addition kept from R12: LAST-kernel egress split across pair lanes
// (both lanes hold the reduced sums after shfl_xor; sub0 writes ch0/ch1
// planes, sub1 writes ch2) — store-side only, arithmetic bit-identical.

constexpr int D = 160;
constexpr int H = 192;
constexpr int W = 160;
constexpr int NVOX = D * H * W;          // 4,915,200
constexpr int NSTEPS = 7;

__device__ __align__(128) float4 g_bufA[NVOX];
__device__ __align__(128) float4 g_bufB[NVOX];

__device__ __forceinline__ void pdl_launch_dependents() {
    asm volatile("griddepcontrol.launch_dependents;" ::: "memory");
}
__device__ __forceinline__ void pdl_wait() {
    asm volatile("griddepcontrol.wait;" ::: "memory");
}

// ---------------------------------------------------------------------------
// Iteration 1, fused with SoA ingest + per-channel voxel-unit scaling.
// One thread per voxel, block = one x-row (160 threads), grid = (H, D).
// ---------------------------------------------------------------------------
__global__ void __launch_bounds__(160)
iter1_kernel(const float* __restrict__ in, float4* __restrict__ out)
{
    int x = threadIdx.x;
    int y = blockIdx.x;
    int z = blockIdx.y;
    int idx = (z * H + y) * W + x;

    pdl_launch_dependents();   // input is external; just let iter2 spin up

    const float s  = 1.0f / 128.0f;          // 1/2^7
    const float sD = s * 0.5f * (D - 1);
    const float sH = s * 0.5f * (H - 1);
    const float sW = s * 0.5f * (W - 1);

    const float* p0 = in;
    const float* p1 = in + NVOX;
    const float* p2 = in + 2 * NVOX;

    float vx = p0[idx] * sD;
    float vy = p1[idx] * sH;
    float vz = p2[idx] * sW;

    float zf = (float)z + vx;
    float yf = (float)y + vy;
    float xf = (float)x + vz;

    int z0 = __float2int_rd(zf);
    int y0 = __float2int_rd(yf);
    int x0 = __float2int_rd(xf);
    float fz = zf - (float)z0;
    float fy = yf - (float)y0;
    float fx = xf - (float)x0;
    int z1 = z0 + 1, y1 = y0 + 1;

    float Wz0 = ((unsigned)z0 < (unsigned)D) ? (1.0f - fz) : 0.0f;
    float Wz1 = ((unsigned)z1 < (unsigned)D) ? fz          : 0.0f;
    float Wy0 = ((unsigned)y0 < (unsigned)H) ? (1.0f - fy) : 0.0f;
    float Wy1 = ((unsigned)y1 < (unsigned)H) ? fy          : 0.0f;
    float Wx0 = ((unsigned)x0 < (unsigned)W) ? (1.0f - fx) : 0.0f;
    float Wx1 = ((unsigned)(x0 + 1) < (unsigned)W) ? fx    : 0.0f;

    int zc0 = min(max(z0, 0), D - 1), zc1 = min(max(z1, 0), D - 1);
    int yc0 = min(max(y0, 0), H - 1), yc1 = min(max(y1, 0), H - 1);
    int xc0 = min(max(x0, 0), W - 1), xc1 = min(max(x0 + 1, 0), W - 1);

    int r00 = (zc0 * H + yc0) * W;
    int r01 = (zc0 * H + yc1) * W;
    int r10 = (zc1 * H + yc0) * W;
    int r11 = (zc1 * H + yc1) * W;

    float px, py, pz;
    {
        const float* p = p0; const float sc = sD;
        float c00a = p[r00 + xc0] * sc, c00b = p[r00 + xc1] * sc;
        float c01a = p[r01 + xc0] * sc, c01b = p[r01 + xc1] * sc;
        float c10a = p[r10 + xc0] * sc, c10b = p[r10 + xc1] * sc;
        float c11a = p[r11 + xc0] * sc, c11b = p[r11 + xc1] * sc;
        float a0A = fmaf(c01a, Wy1, c00a * Wy0);
        float a1A = fmaf(c11a, Wy1, c10a * Wy0);
        float a0B = fmaf(c01b, Wy1, c00b * Wy0);
        float a1B = fmaf(c11b, Wy1, c10b * Wy0);
        px = Wx0 * fmaf(a1A, Wz1, a0A * Wz0)
           + Wx1 * fmaf(a1B, Wz1, a0B * Wz0);
    }
    {
        const float* p = p1; const float sc = sH;
        float c00a = p[r00 + xc0] * sc, c00b = p[r00 + xc1] * sc;
        float c01a = p[r01 + xc0] * sc, c01b = p[r01 + xc1] * sc;
        float c10a = p[r10 + xc0] * sc, c10b = p[r10 + xc1] * sc;
        float c11a = p[r11 + xc0] * sc, c11b = p[r11 + xc1] * sc;
        float a0A = fmaf(c01a, Wy1, c00a * Wy0);
        float a1A = fmaf(c11a, Wy1, c10a * Wy0);
        float a0B = fmaf(c01b, Wy1, c00b * Wy0);
        float a1B = fmaf(c11b, Wy1, c10b * Wy0);
        py = Wx0 * fmaf(a1A, Wz1, a0A * Wz0)
           + Wx1 * fmaf(a1B, Wz1, a0B * Wz0);
    }
    {
        const float* p = p2; const float sc = sW;
        float c00a = p[r00 + xc0] * sc, c00b = p[r00 + xc1] * sc;
        float c01a = p[r01 + xc0] * sc, c01b = p[r01 + xc1] * sc;
        float c10a = p[r10 + xc0] * sc, c10b = p[r10 + xc1] * sc;
        float c11a = p[r11 + xc0] * sc, c11b = p[r11 + xc1] * sc;
        float a0A = fmaf(c01a, Wy1, c00a * Wy0);
        float a1A = fmaf(c11a, Wy1, c10a * Wy0);
        float a0B = fmaf(c01b, Wy1, c00b * Wy0);
        float a1B = fmaf(c11b, Wy1, c10b * Wy0);
        pz = Wx0 * fmaf(a1A, Wz1, a0A * Wz0)
           + Wx1 * fmaf(a1B, Wz1, a0B * Wz0);
    }

    out[idx] = make_float4(vx + px, vy + py, vz + pz, 0.0f);
}

// ---------------------------------------------------------------------------
// Iterations 2-7: pair-lane scheme. One x-row per block, 320 threads =
// 160 voxels * 2 lanes; even lane takes x0 corners, odd lane x1.
// ---------------------------------------------------------------------------
template<bool LAST>
__global__ void __launch_bounds__(320)
integrate_kernel(const float4* __restrict__ in, float4* __restrict__ out4,
                 float* __restrict__ out_soa)
{
    int x   = threadIdx.x >> 1;
    int sub = threadIdx.x & 1;
    int y   = blockIdx.x;
    int z   = blockIdx.y;
    int idx = (z * H + y) * W + x;

    pdl_launch_dependents();
    pdl_wait();

    float4 v = in[idx];   // same address in both pair lanes -> broadcast

    float zf = (float)z + v.x;
    float yf = (float)y + v.y;
    float xf = (float)x + v.z;

    int z0 = __float2int_rd(zf);
    int y0 = __float2int_rd(yf);
    int x0 = __float2int_rd(xf);
    float fz = zf - (float)z0;
    float fy = yf - (float)y0;
    float fx = xf - (float)x0;
    int z1 = z0 + 1, y1 = y0 + 1;

    float Wz0 = ((unsigned)z0 < (unsigned)D) ? (1.0f - fz) : 0.0f;
    float Wz1 = ((unsigned)z1 < (unsigned)D) ? fz          : 0.0f;
    float Wy0 = ((unsigned)y0 < (unsigned)H) ? (1.0f - fy) : 0.0f;
    float Wy1 = ((unsigned)y1 < (unsigned)H) ? fy          : 0.0f;
    float Wx0 = ((unsigned)x0 < (unsigned)W) ? (1.0f - fx) : 0.0f;
    float Wx1 = ((unsigned)(x0 + 1) < (unsigned)W) ? fx    : 0.0f;

    int zc0 = min(max(z0, 0), D - 1), zc1 = min(max(z1, 0), D - 1);
    int yc0 = min(max(y0, 0), H - 1), yc1 = min(max(y1, 0), H - 1);
    int xc0 = min(max(x0, 0), W - 1), xc1 = min(max(x0 + 1, 0), W - 1);

    int   xc = sub ? xc1 : xc0;
    float wx = sub ? Wx1 : Wx0;

    int r00 = (zc0 * H + yc0) * W + xc;
    int r01 = (zc0 * H + yc1) * W + xc;
    int r10 = (zc1 * H + yc0) * W + xc;
    int r11 = (zc1 * H + yc1) * W + xc;

    float4 c00 = in[r00];
    float4 c01 = in[r01];
    float4 c10 = in[r10];
    float4 c11 = in[r11];

    float px, py, pz;
    {
        float a0 = fmaf(c01.x, Wy1, c00.x * Wy0);
        float a1 = fmaf(c11.x, Wy1, c10.x * Wy0);
        px = wx * fmaf(a1, Wz1, a0 * Wz0);
    }
    {
        float a0 = fmaf(c01.y, Wy1, c00.y * Wy0);
        float a1 = fmaf(c11.y, Wy1, c10.y * Wy0);
        py = wx * fmaf(a1, Wz1, a0 * Wz0);
    }
    {
        float a0 = fmaf(c01.z, Wy1, c00.z * Wy0);
        float a1 = fmaf(c11.z, Wy1, c10.z * Wy0);
        pz = wx * fmaf(a1, Wz1, a0 * Wz0);
    }
    px += __shfl_xor_sync(0xFFFFFFFFu, px, 1);
    py += __shfl_xor_sync(0xFFFFFFFFu, py, 1);
    pz += __shfl_xor_sync(0xFFFFFFFFu, pz, 1);

    if (!LAST) {
        if (sub == 0) {
            float4 r;
            r.x = v.x + px;
            r.y = v.y + py;
            r.z = v.z + pz;
            r.w = 0.0f;
            out4[idx] = r;
        }
    } else {
        // both lanes hold the reduced sums; split the 3 plane stores
        if (sub == 0) {
            out_soa[idx]            = (v.x + px) * (1.0f / (0.5f * (D - 1)));
            out_soa[idx + NVOX]     = (v.y + py) * (1.0f / (0.5f * (H - 1)));
        } else {
            out_soa[idx + 2 * NVOX] = (v.z + pz) * (1.0f / (0.5f * (W - 1)));
        }
    }
}

static void launch_pdl(void* func, dim3 grid, dim3 block, void** args)
{
    cudaLaunchConfig_t cfg = {};
    cfg.gridDim  = grid;
    cfg.blockDim = block;
    cfg.dynamicSmemBytes = 0;
    cfg.stream = 0;
    cudaLaunchAttribute attr[1];
    attr[0].id = cudaLaunchAttributeProgrammaticStreamSerialization;
    attr[0].val.programmaticStreamSerializationAllowed = 1;
    cfg.attrs = attr;
    cfg.numAttrs = 1;
    cudaLaunchKernelExC(&cfg, func, args);
}

extern "C" void kernel_launch(void* const* d_in, const int* in_sizes, int n_in,
                              void* d_out, int out_size)
{
    const float* vec = (const float*)d_in[0];
    float* out = (float*)d_out;

    float4 *bufA, *bufB;
    cudaGetSymbolAddress((void**)&bufA, g_bufA);
    cudaGetSymbolAddress((void**)&bufB, g_bufB);

    dim3 grid(H, D);                 // (y, z)

    // iteration 1, fused with ingest/scaling
    {
        const float* a0 = vec; float4* a1 = bufA;
        void* args[] = { &a0, &a1 };
        launch_pdl((void*)iter1_kernel, grid, dim3(W), args);
    }

    // iterations 2..6
    float4* cur = bufA;
    float4* nxt = bufB;
    for (int i = 0; i < NSTEPS - 2; ++i) {
        const float4* a0 = cur; float4* a1 = nxt; float* a2 = nullptr;
        void* args[] = { &a0, &a1, &a2 };
        launch_pdl((void*)integrate_kernel<false>, grid, dim3(2 * W), args);
        float4* tmp = cur; cur = nxt; nxt = tmp;
    }
    // iteration 7, fused with SoA scale-out
    {
        const float4* a0 = cur; float4* a1 = nullptr; float* a2 = out;
        void* args[] = { &a0, &a1, &a2 };
        launch_pdl((void*)integrate_kernel<true>, grid, dim3(2 * W), args);
    }
}